// round 2
// baseline (speedup 1.0000x reference)
#include <cuda_runtime.h>

// TransD forward, simplified (eye is 128x128 identity, RD==ED):
//   h_out = renorm(rp) * <renorm(hp), renorm(hv)> + renorm(hv)
//   rv_out = renorm(rv)
//   t_out = renorm(rp) * <renorm(tp), renorm(tv)> + renorm(tv)
//
// ILP=2: one warp processes 2 samples -> 12 float4 gathers in flight,
// 16 shfl reduction chains pipelined. Lane owns one float4 of each row.

#define NB 8192
#define DV 32  // float4s per 128-float row

__device__ __forceinline__ float warp_sum(float v) {
    v += __shfl_xor_sync(0xffffffffu, v, 16);
    v += __shfl_xor_sync(0xffffffffu, v, 8);
    v += __shfl_xor_sync(0xffffffffu, v, 4);
    v += __shfl_xor_sync(0xffffffffu, v, 2);
    v += __shfl_xor_sync(0xffffffffu, v, 1);
    return v;
}

__device__ __forceinline__ float dot4(float4 a, float4 b) {
    return a.x * b.x + a.y * b.y + a.z * b.z + a.w * b.w;
}

__device__ __forceinline__ float rscale(float sumsq) {
    float n = sqrtf(sumsq);
    return (n > 1.0f) ? (1.0f / (n + 1e-7f)) : 1.0f;
}

__global__ __launch_bounds__(256) void transd_kernel(
    const float4* __restrict__ ee,   // entity_emb      [ENT*32]
    const float4* __restrict__ eep,  // entity_emb_p    [ENT*32]
    const float4* __restrict__ re,   // relation_emb    [REL*32]
    const float4* __restrict__ rep,  // relation_emb_p  [REL*32]
    const int* __restrict__ h,
    const int* __restrict__ r,
    const int* __restrict__ t,
    float4* __restrict__ out)        // [3 * NB * 32]
{
    int gwarp = (blockIdx.x * blockDim.x + threadIdx.x) >> 5;
    int lane = threadIdx.x & 31;
    int s0 = gwarp * 2;
    int s1 = s0 + 1;
    if (s0 >= NB) return;

    // indices (broadcast loads, L1/L2 resident)
    int hi0 = h[s0], hi1 = h[s1];
    int ri0 = r[s0], ri1 = r[s1];
    int ti0 = t[s0], ti1 = t[s1];

    // issue all 12 gathers up front for max MLP
    float4 hv0 = ee [(long)hi0 * DV + lane];
    float4 hv1 = ee [(long)hi1 * DV + lane];
    float4 hp0 = eep[(long)hi0 * DV + lane];
    float4 hp1 = eep[(long)hi1 * DV + lane];
    float4 tv0 = ee [(long)ti0 * DV + lane];
    float4 tv1 = ee [(long)ti1 * DV + lane];
    float4 tp0 = eep[(long)ti0 * DV + lane];
    float4 tp1 = eep[(long)ti1 * DV + lane];
    float4 rv0 = __ldg(&re [(long)ri0 * DV + lane]);
    float4 rv1 = __ldg(&re [(long)ri1 * DV + lane]);
    float4 rp0 = __ldg(&rep[(long)ri0 * DV + lane]);
    float4 rp1 = __ldg(&rep[(long)ri1 * DV + lane]);

    // 16 reductions, interleaved so the shfl chains pipeline
    float s_hv0 = warp_sum(dot4(hv0, hv0));
    float s_hv1 = warp_sum(dot4(hv1, hv1));
    float s_hp0 = warp_sum(dot4(hp0, hp0));
    float s_hp1 = warp_sum(dot4(hp1, hp1));
    float s_tv0 = warp_sum(dot4(tv0, tv0));
    float s_tv1 = warp_sum(dot4(tv1, tv1));
    float s_tp0 = warp_sum(dot4(tp0, tp0));
    float s_tp1 = warp_sum(dot4(tp1, tp1));
    float s_rv0 = warp_sum(dot4(rv0, rv0));
    float s_rv1 = warp_sum(dot4(rv1, rv1));
    float s_rp0 = warp_sum(dot4(rp0, rp0));
    float s_rp1 = warp_sum(dot4(rp1, rp1));
    float d_h0  = warp_sum(dot4(hp0, hv0));
    float d_h1  = warp_sum(dot4(hp1, hv1));
    float d_t0  = warp_sum(dot4(tp0, tv0));
    float d_t1  = warp_sum(dot4(tp1, tv1));

    float c_hv0 = rscale(s_hv0), c_hv1 = rscale(s_hv1);
    float c_hp0 = rscale(s_hp0), c_hp1 = rscale(s_hp1);
    float c_tv0 = rscale(s_tv0), c_tv1 = rscale(s_tv1);
    float c_tp0 = rscale(s_tp0), c_tp1 = rscale(s_tp1);
    float c_rv0 = rscale(s_rv0), c_rv1 = rscale(s_rv1);
    float c_rp0 = rscale(s_rp0), c_rp1 = rscale(s_rp1);

    float a_h0 = c_rp0 * d_h0 * c_hp0 * c_hv0;
    float a_h1 = c_rp1 * d_h1 * c_hp1 * c_hv1;
    float a_t0 = c_rp0 * d_t0 * c_tp0 * c_tv0;
    float a_t1 = c_rp1 * d_t1 * c_tp1 * c_tv1;

    long b0 = (long)s0 * DV + lane;
    long b1 = (long)s1 * DV + lane;

    float4 o;
    // h_out
    o.x = rp0.x * a_h0 + hv0.x * c_hv0;
    o.y = rp0.y * a_h0 + hv0.y * c_hv0;
    o.z = rp0.z * a_h0 + hv0.z * c_hv0;
    o.w = rp0.w * a_h0 + hv0.w * c_hv0;
    out[b0] = o;
    o.x = rp1.x * a_h1 + hv1.x * c_hv1;
    o.y = rp1.y * a_h1 + hv1.y * c_hv1;
    o.z = rp1.z * a_h1 + hv1.z * c_hv1;
    o.w = rp1.w * a_h1 + hv1.w * c_hv1;
    out[b1] = o;

    // rv
    o.x = rv0.x * c_rv0; o.y = rv0.y * c_rv0; o.z = rv0.z * c_rv0; o.w = rv0.w * c_rv0;
    out[(long)NB * DV + b0] = o;
    o.x = rv1.x * c_rv1; o.y = rv1.y * c_rv1; o.z = rv1.z * c_rv1; o.w = rv1.w * c_rv1;
    out[(long)NB * DV + b1] = o;

    // t_out
    o.x = rp0.x * a_t0 + tv0.x * c_tv0;
    o.y = rp0.y * a_t0 + tv0.y * c_tv0;
    o.z = rp0.z * a_t0 + tv0.z * c_tv0;
    o.w = rp0.w * a_t0 + tv0.w * c_tv0;
    out[2L * NB * DV + b0] = o;
    o.x = rp1.x * a_t1 + tv1.x * c_tv1;
    o.y = rp1.y * a_t1 + tv1.y * c_tv1;
    o.z = rp1.z * a_t1 + tv1.z * c_tv1;
    o.w = rp1.w * a_t1 + tv1.w * c_tv1;
    out[2L * NB * DV + b1] = o;
}

extern "C" void kernel_launch(void* const* d_in, const int* in_sizes, int n_in,
                              void* d_out, int out_size) {
    const float4* ee  = (const float4*)d_in[0];
    const float4* eep = (const float4*)d_in[1];
    const float4* re  = (const float4*)d_in[2];
    const float4* rep = (const float4*)d_in[3];
    const int* h = (const int*)d_in[4];
    const int* r = (const int*)d_in[5];
    const int* t = (const int*)d_in[6];

    // 2 samples per warp -> 4096 warps -> 512 blocks of 256 threads
    int warps = NB / 2;
    int blocks = (warps * 32 + 255) / 256;
    transd_kernel<<<blocks, 256>>>(ee, eep, re, rep, h, r, t, (float4*)d_out);
}

// round 4
// speedup vs baseline: 1.2325x; 1.2325x over previous
#include <cuda_runtime.h>

// TransD forward, simplified (eye is identity, RD==ED):
//   h_out = renorm(rp) * <renorm(hp), renorm(hv)> + renorm(hv)
//   rv_out = renorm(rv)
//   t_out = renorm(rp) * <renorm(tp), renorm(tv)> + renorm(tv)
//
// One warp per sample, lane owns one float4.
// Multiplexed 8-value warp reduction: 30 SHFL instead of 40, shorter chains.

#define NB 8192
#define DV 32  // float4s per 128-float row
#define FULL 0xffffffffu

__device__ __forceinline__ float dot4(float4 a, float4 b) {
    return a.x * b.x + a.y * b.y + a.z * b.z + a.w * b.w;
}

__device__ __forceinline__ float rscale(float sumsq) {
    float n = sqrtf(sumsq);
    return (n > 1.0f) ? (1.0f / (n + 1e-7f)) : 1.0f;
}

__device__ __forceinline__ void st_cs(float4* p, float4 v) {
    asm volatile("st.global.cs.v4.f32 [%0], {%1,%2,%3,%4};"
                 :: "l"(p), "f"(v.x), "f"(v.y), "f"(v.z), "f"(v.w) : "memory");
}

__global__ __launch_bounds__(256) void transd_kernel(
    const float4* __restrict__ ee,   // entity_emb      [ENT*32]
    const float4* __restrict__ eep,  // entity_emb_p    [ENT*32]
    const float4* __restrict__ re,   // relation_emb    [REL*32]
    const float4* __restrict__ rep,  // relation_emb_p  [REL*32]
    const int* __restrict__ h,
    const int* __restrict__ r,
    const int* __restrict__ t,
    float4* __restrict__ out)        // [3 * NB * 32]
{
    int gwarp = (blockIdx.x * blockDim.x + threadIdx.x) >> 5;
    int lane = threadIdx.x & 31;
    if (gwarp >= NB) return;

    int hi = h[gwarp];
    int ri = r[gwarp];
    int ti = t[gwarp];

    // all 6 gathers issued up front (max MLP)
    float4 hv = __ldg(&ee [(long)hi * DV + lane]);
    float4 hp = __ldg(&eep[(long)hi * DV + lane]);
    float4 tv = __ldg(&ee [(long)ti * DV + lane]);
    float4 tp = __ldg(&eep[(long)ti * DV + lane]);
    float4 rv = __ldg(&re [(long)ri * DV + lane]);
    float4 rp = __ldg(&rep[(long)ri * DV + lane]);

    // per-lane partials for the 8 reductions
    float p0 = dot4(hv, hv);
    float p1 = dot4(hp, hp);
    float p2 = dot4(tv, tv);
    float p3 = dot4(tp, tp);
    float p4 = dot4(rv, rv);
    float p5 = dot4(rp, rp);
    float p6 = dot4(hp, hv);
    float p7 = dot4(tp, tv);

    // Stage A: reduce each value within groups of 4 lanes (xor 1, 2)
    p0 += __shfl_xor_sync(FULL, p0, 1); p0 += __shfl_xor_sync(FULL, p0, 2);
    p1 += __shfl_xor_sync(FULL, p1, 1); p1 += __shfl_xor_sync(FULL, p1, 2);
    p2 += __shfl_xor_sync(FULL, p2, 1); p2 += __shfl_xor_sync(FULL, p2, 2);
    p3 += __shfl_xor_sync(FULL, p3, 1); p3 += __shfl_xor_sync(FULL, p3, 2);
    p4 += __shfl_xor_sync(FULL, p4, 1); p4 += __shfl_xor_sync(FULL, p4, 2);
    p5 += __shfl_xor_sync(FULL, p5, 1); p5 += __shfl_xor_sync(FULL, p5, 2);
    p6 += __shfl_xor_sync(FULL, p6, 1); p6 += __shfl_xor_sync(FULL, p6, 2);
    p7 += __shfl_xor_sync(FULL, p7, 1); p7 += __shfl_xor_sync(FULL, p7, 2);

    // Stage B/C: lane (l&3) carries value k / value 4+k through xor 4, 8, 16
    int q = lane & 3;
    float w1 = (q & 2) ? ((q & 1) ? p3 : p2) : ((q & 1) ? p1 : p0);
    float w2 = (q & 2) ? ((q & 1) ? p7 : p6) : ((q & 1) ? p5 : p4);
    w1 += __shfl_xor_sync(FULL, w1, 4);
    w2 += __shfl_xor_sync(FULL, w2, 4);
    w1 += __shfl_xor_sync(FULL, w1, 8);
    w2 += __shfl_xor_sync(FULL, w2, 8);
    w1 += __shfl_xor_sync(FULL, w1, 16);
    w2 += __shfl_xor_sync(FULL, w2, 16);
    // now w1 = total_{lane&3}, w2 = total_{4+(lane&3)} in every lane

    // broadcast the 8 totals
    float s_hv = __shfl_sync(FULL, w1, 0);
    float s_hp = __shfl_sync(FULL, w1, 1);
    float s_tv = __shfl_sync(FULL, w1, 2);
    float s_tp = __shfl_sync(FULL, w1, 3);
    float s_rv = __shfl_sync(FULL, w2, 0);
    float s_rp = __shfl_sync(FULL, w2, 1);
    float d_h  = __shfl_sync(FULL, w2, 2);
    float d_t  = __shfl_sync(FULL, w2, 3);

    float c_hv = rscale(s_hv);
    float c_tv = rscale(s_tv);
    float c_rv = rscale(s_rv);
    float a_h = rscale(s_rp) * (d_h * rscale(s_hp) * c_hv);
    float a_t = rscale(s_rp) * (d_t * rscale(s_tp) * c_tv);

    long base = (long)gwarp * DV + lane;

    float4 o;
    o.x = rp.x * a_h + hv.x * c_hv;
    o.y = rp.y * a_h + hv.y * c_hv;
    o.z = rp.z * a_h + hv.z * c_hv;
    o.w = rp.w * a_h + hv.w * c_hv;
    st_cs(&out[base], o);

    o.x = rv.x * c_rv; o.y = rv.y * c_rv; o.z = rv.z * c_rv; o.w = rv.w * c_rv;
    st_cs(&out[(long)NB * DV + base], o);

    o.x = rp.x * a_t + tv.x * c_tv;
    o.y = rp.y * a_t + tv.y * c_tv;
    o.z = rp.z * a_t + tv.z * c_tv;
    o.w = rp.w * a_t + tv.w * c_tv;
    st_cs(&out[2L * NB * DV + base], o);
}

extern "C" void kernel_launch(void* const* d_in, const int* in_sizes, int n_in,
                              void* d_out, int out_size) {
    const float4* ee  = (const float4*)d_in[0];
    const float4* eep = (const float4*)d_in[1];
    const float4* re  = (const float4*)d_in[2];
    const float4* rep = (const float4*)d_in[3];
    const int* h = (const int*)d_in[4];
    const int* r = (const int*)d_in[5];
    const int* t = (const int*)d_in[6];

    int blocks = (NB * 32 + 255) / 256;
    transd_kernel<<<blocks, 256>>>(ee, eep, re, rep, h, r, t, (float4*)d_out);
}

// round 5
// speedup vs baseline: 1.2370x; 1.0037x over previous
#include <cuda_runtime.h>

// TransD forward, simplified (eye is identity, RD==ED):
//   h_out = renorm(rp) * <renorm(hp), renorm(hv)> + renorm(hv)
//   rv_out = renorm(rv)
//   t_out = renorm(rp) * <renorm(tp), renorm(tv)> + renorm(tv)
//
// Two warps per sample: side 0 computes h_out + rv_out, side 1 computes t_out.
// Shorter per-warp chains (3-4 gathers, 4-5 reductions) for better latency hiding.

#define NB 8192
#define DV 32  // float4s per 128-float row
#define FULL 0xffffffffu

__device__ __forceinline__ float dot4(float4 a, float4 b) {
    return a.x * b.x + a.y * b.y + a.z * b.z + a.w * b.w;
}

__device__ __forceinline__ float rscale(float sumsq) {
    float n = sqrtf(sumsq);
    return (n > 1.0f) ? (1.0f / (n + 1e-7f)) : 1.0f;
}

__device__ __forceinline__ void st_cs(float4* p, float4 v) {
    asm volatile("st.global.cs.v4.f32 [%0], {%1,%2,%3,%4};"
                 :: "l"(p), "f"(v.x), "f"(v.y), "f"(v.z), "f"(v.w) : "memory");
}

__global__ __launch_bounds__(256) void transd_kernel(
    const float4* __restrict__ ee,   // entity_emb      [ENT*32]
    const float4* __restrict__ eep,  // entity_emb_p    [ENT*32]
    const float4* __restrict__ re,   // relation_emb    [REL*32]
    const float4* __restrict__ rep,  // relation_emb_p  [REL*32]
    const int* __restrict__ h,
    const int* __restrict__ r,
    const int* __restrict__ t,
    float4* __restrict__ out)        // [3 * NB * 32]
{
    int gw = (blockIdx.x * blockDim.x + threadIdx.x) >> 5;
    int lane = threadIdx.x & 31;
    int s = gw >> 1;        // sample
    int side = gw & 1;      // 0 = h-side (+rv), 1 = t-side
    if (s >= NB) return;

    int ri = r[s];
    int ei = side ? t[s] : h[s];

    // gathers up front
    float4 ev = __ldg(&ee [(long)ei * DV + lane]);   // hv or tv
    float4 ep = __ldg(&eep[(long)ei * DV + lane]);   // hp or tp
    float4 rp = __ldg(&rep[(long)ri * DV + lane]);
    float4 rv;
    if (!side) rv = __ldg(&re[(long)ri * DV + lane]);

    // 4 (or 5) reductions
    float p0 = dot4(ev, ev);
    float p1 = dot4(ep, ep);
    float p2 = dot4(rp, rp);
    float p3 = dot4(ep, ev);

    // stage A: reduce within groups of 4 lanes
    p0 += __shfl_xor_sync(FULL, p0, 1); p0 += __shfl_xor_sync(FULL, p0, 2);
    p1 += __shfl_xor_sync(FULL, p1, 1); p1 += __shfl_xor_sync(FULL, p1, 2);
    p2 += __shfl_xor_sync(FULL, p2, 1); p2 += __shfl_xor_sync(FULL, p2, 2);
    p3 += __shfl_xor_sync(FULL, p3, 1); p3 += __shfl_xor_sync(FULL, p3, 2);

    // stage B: lane (l&3) carries value q through xor 4, 8, 16
    int q = lane & 3;
    float w = (q & 2) ? ((q & 1) ? p3 : p2) : ((q & 1) ? p1 : p0);
    w += __shfl_xor_sync(FULL, w, 4);
    w += __shfl_xor_sync(FULL, w, 8);
    w += __shfl_xor_sync(FULL, w, 16);

    float s_ev = __shfl_sync(FULL, w, 0);
    float s_ep = __shfl_sync(FULL, w, 1);
    float s_rp = __shfl_sync(FULL, w, 2);
    float d    = __shfl_sync(FULL, w, 3);

    // rv norm (side 0 only; warp-uniform branch)
    float s_rv = 0.0f;
    if (!side) {
        float pr = dot4(rv, rv);
        pr += __shfl_xor_sync(FULL, pr, 1);
        pr += __shfl_xor_sync(FULL, pr, 2);
        pr += __shfl_xor_sync(FULL, pr, 4);
        pr += __shfl_xor_sync(FULL, pr, 8);
        pr += __shfl_xor_sync(FULL, pr, 16);
        s_rv = pr;
    }

    float c_ev = rscale(s_ev);
    float a = rscale(s_rp) * (d * rscale(s_ep) * c_ev);

    long base = (long)s * DV + lane;

    float4 o;
    o.x = rp.x * a + ev.x * c_ev;
    o.y = rp.y * a + ev.y * c_ev;
    o.z = rp.z * a + ev.z * c_ev;
    o.w = rp.w * a + ev.w * c_ev;
    st_cs(&out[side ? (2L * NB * DV + base) : base], o);

    if (!side) {
        float c_rv = rscale(s_rv);
        o.x = rv.x * c_rv; o.y = rv.y * c_rv;
        o.z = rv.z * c_rv; o.w = rv.w * c_rv;
        st_cs(&out[(long)NB * DV + base], o);
    }
}

extern "C" void kernel_launch(void* const* d_in, const int* in_sizes, int n_in,
                              void* d_out, int out_size) {
    const float4* ee  = (const float4*)d_in[0];
    const float4* eep = (const float4*)d_in[1];
    const float4* re  = (const float4*)d_in[2];
    const float4* rep = (const float4*)d_in[3];
    const int* h = (const int*)d_in[4];
    const int* r = (const int*)d_in[5];
    const int* t = (const int*)d_in[6];

    // 2 warps per sample -> 16384 warps -> 2048 blocks of 256 threads
    int blocks = (2 * NB * 32 + 255) / 256;
    transd_kernel<<<blocks, 256>>>(ee, eep, re, rep, h, r, t, (float4*)d_out);
}